// round 13
// baseline (speedup 1.0000x reference)
#include <cuda_runtime.h>
#include <cuda_bf16.h>
#include <cstdint>

// Problem constants
#define NB     4
#define HH     64
#define WW     64
#define EMBED  128
#define NH     4
#define HD     32
#define CTX    256
#define RANK   8
#define KER    7
#define K2     49
#define PAD    3
#define SCALE  0.17677669529663689f   // 32^-0.5
#define TOK    4096                   // tokens per batch (64*64)
#define NTOK   16384                  // total tokens

// ---------------- device scratch (static allocation: allowed) ----------------
__device__ float g_c2[NB * RANK];                 // alpha_b * c_proj[b][r]
__device__ float g_qkv[3 * NB * NH * TOK * HD];   // [s][b][h][tok][d]
__device__ float g_attn[NTOK * EMBED];            // [tok][h*32+d]
// pre-split weights (bf16 hi/lo)
__device__ __align__(16) unsigned short g_wh[NB * 3 * EMBED * EMBED];
__device__ __align__(16) unsigned short g_wl[NB * 3 * EMBED * EMBED];
__device__ __align__(16) unsigned short g_ph[EMBED * EMBED];
__device__ __align__(16) unsigned short g_pl[EMBED * EMBED];

// ---------------- kernel 0: c2 = alpha * (context @ Blora) -------------------
__global__ void prep_kernel(const float* __restrict__ ctx,
                            const float* __restrict__ Blora,
                            const float* __restrict__ g1w,
                            const float* __restrict__ g1b,
                            const float* __restrict__ g2w,
                            const float* __restrict__ g2b) {
    __shared__ float scp[32];
    __shared__ float sh[64];
    __shared__ float sal[4];
    int t = threadIdx.x;
    if (t < 32) {
        int b = t >> 3, r = t & 7;
        float s = 0.f;
        #pragma unroll 4
        for (int c = 0; c < CTX; ++c)
            s = fmaf(ctx[b * CTX + c], Blora[c * RANK + r], s);
        scp[t] = s;
    } else if (t >= 64) {
        int u = t - 64;
        int b = u >> 4, j = u & 15;
        float hj = g1b[j];
        #pragma unroll 4
        for (int c = 0; c < CTX; ++c)
            hj = fmaf(ctx[b * CTX + c], g1w[j * CTX + c], hj);
        sh[u] = fmaxf(hj, 0.f) * g2w[j];
    }
    __syncthreads();
    if (t < 4) {
        float s = g2b[0];
        #pragma unroll
        for (int j = 0; j < 16; ++j) s += sh[t * 16 + j];
        sal[t] = 1.f / (1.f + __expf(-s));
    }
    __syncthreads();
    if (t < 32) g_c2[t] = sal[t >> 3] * scp[t];
}

// ---------------- split helpers ----------------------------------------------
__device__ __forceinline__ void split4(float4 v, ushort4& h, ushort4& l) {
    __nv_bfloat16 hx = __float2bfloat16_rn(v.x);
    __nv_bfloat16 hy = __float2bfloat16_rn(v.y);
    __nv_bfloat16 hz = __float2bfloat16_rn(v.z);
    __nv_bfloat16 hw = __float2bfloat16_rn(v.w);
    h = make_ushort4(__bfloat16_as_ushort(hx), __bfloat16_as_ushort(hy),
                     __bfloat16_as_ushort(hz), __bfloat16_as_ushort(hw));
    l = make_ushort4(
        __bfloat16_as_ushort(__float2bfloat16_rn(v.x - __bfloat162float(hx))),
        __bfloat16_as_ushort(__float2bfloat16_rn(v.y - __bfloat162float(hy))),
        __bfloat16_as_ushort(__float2bfloat16_rn(v.z - __bfloat162float(hz))),
        __bfloat16_as_ushort(__float2bfloat16_rn(v.w - __bfloat162float(hw))));
}
__device__ __forceinline__ void split2(float x, float y, uint32_t& hi, uint32_t& lo) {
    __nv_bfloat16 hx = __float2bfloat16_rn(x);
    __nv_bfloat16 hy = __float2bfloat16_rn(y);
    __nv_bfloat16 lx = __float2bfloat16_rn(x - __bfloat162float(hx));
    __nv_bfloat16 ly = __float2bfloat16_rn(y - __bfloat162float(hy));
    hi = ((uint32_t)__bfloat16_as_ushort(hy) << 16) | __bfloat16_as_ushort(hx);
    lo = ((uint32_t)__bfloat16_as_ushort(ly) << 16) | __bfloat16_as_ushort(lx);
}

// -------- kernel 1: W_eff = Wqkv + Vlora diag(c2) A^T -> bf16 hi/lo ----------
// blocks [0,192): Weff (49152 float4); [192,208): Wproj (4096 float4)
__global__ void weff_kernel(const float* __restrict__ Wqkv,
                            const float* __restrict__ A,
                            const float* __restrict__ Vl,
                            const float* __restrict__ Wproj) {
    int blk = blockIdx.x, tid = threadIdx.x;
    if (blk < 192) {
        int id = blk * 256 + tid;               // float4 index over [b][o][i]
        int b = id / 12288;
        int rid = id - b * 12288;
        float4 w = ((const float4*)Wqkv)[rid];
        int e0 = rid * 4;
        int o = e0 >> 7, i = e0 & 127;
        const float* c2 = g_c2 + b * RANK;
        #pragma unroll
        for (int r = 0; r < RANK; ++r) {
            float vc = Vl[o * RANK + r] * c2[r];
            w.x = fmaf(vc, A[(i + 0) * RANK + r], w.x);
            w.y = fmaf(vc, A[(i + 1) * RANK + r], w.y);
            w.z = fmaf(vc, A[(i + 2) * RANK + r], w.z);
            w.w = fmaf(vc, A[(i + 3) * RANK + r], w.w);
        }
        ushort4 h, l; split4(w, h, l);
        ((ushort4*)g_wh)[id] = h;
        ((ushort4*)g_wl)[id] = l;
    } else {
        int id = (blk - 192) * 256 + tid;       // 4096 float4
        float4 v = ((const float4*)Wproj)[id];
        ushort4 h, l; split4(v, h, l);
        ((ushort4*)g_ph)[id] = h;
        ((ushort4*)g_pl)[id] = l;
    }
}

// ================== bf16x3 tensor-core GEMM (mma.sync path) ==================
// C[m][n] = sum_k A[m][k]*B[n][k]. A fp32 in gmem (split in-CTA); B pre-split
// bf16 hi/lo in gmem (pure copy to smem). Tile 64(M) x 128(N) x 128(K).
// smem = 104448B -> 2 CTAs/SM. 8 warps in 2(m) x 4(n), each 32x32.
#define RSTRIDE 272
#define SM_AHI  0
#define SM_ALO  (64 * RSTRIDE)                  // 17408
#define SM_BHI  (2 * 64 * RSTRIDE)              // 34816
#define SM_BLO  (SM_BHI + 128 * RSTRIDE)        // 69632
#define GEMM_SMEM (SM_BLO + 128 * RSTRIDE)      // 104448

__device__ __forceinline__ uint32_t smem_u32(const void* p) {
    uint32_t a;
    asm("{ .reg .u64 t; cvta.to.shared.u64 t, %1; cvt.u32.u64 %0, t; }"
        : "=r"(a) : "l"(p));
    return a;
}

#define LDM4(r, addr) \
    asm volatile("ldmatrix.sync.aligned.m8n8.x4.shared.b16 {%0,%1,%2,%3}, [%4];" \
        : "=r"((r)[0]), "=r"((r)[1]), "=r"((r)[2]), "=r"((r)[3]) : "r"(addr))

#define MMA_BF16(c, a, b0, b1) \
    asm volatile("mma.sync.aligned.m16n8k16.row.col.f32.bf16.bf16.f32 " \
        "{%0,%1,%2,%3}, {%4,%5,%6,%7}, {%8,%9}, {%0,%1,%2,%3};" \
        : "+f"((c)[0]), "+f"((c)[1]), "+f"((c)[2]), "+f"((c)[3]) \
        : "r"((a)[0]), "r"((a)[1]), "r"((a)[2]), "r"((a)[3]), "r"(b0), "r"(b1))

template <bool QKV>
__global__ __launch_bounds__(256, 2)
void gemm_mma(const float* __restrict__ Aglob,
              const float* __restrict__ bias,
              float* __restrict__ outp) {
    extern __shared__ char smem[];
    const uint32_t sbase = smem_u32(smem);
    const int tid  = threadIdx.x;
    const int wid  = tid >> 5;
    const int lane = tid & 31;
    const int mw  = wid >> 2;         // 0..1 (m half)
    const int nw2 = wid & 3;          // 0..3 (n quarter)
    const int b  = blockIdx.z;
    const int m0 = blockIdx.x * 64;
    const int n0 = blockIdx.y * 128;

    const float* srcA = QKV ? Aglob + ((size_t)b * TOK + m0) * EMBED
                            : g_attn + (size_t)m0 * EMBED;
    const unsigned short* Bh = QKV ? g_wh + (size_t)b * 3 * EMBED * EMBED + (size_t)n0 * EMBED
                                   : g_ph;
    const unsigned short* Bl = QKV ? g_wl + (size_t)b * 3 * EMBED * EMBED + (size_t)n0 * EMBED
                                   : g_pl;

    // ---- fill A (64x128 fp32 -> hi/lo bf16), 2048 float4 / 256 thr ----
    #pragma unroll
    for (int it = 0; it < 8; ++it) {
        int idx = it * 256 + tid;
        int row = idx >> 5, c4 = idx & 31;
        float4 v = *(const float4*)(srcA + (size_t)row * EMBED + c4 * 4);
        uint32_t h0, l0, h1, l1;
        split2(v.x, v.y, h0, l0);
        split2(v.z, v.w, h1, l1);
        uint32_t off = row * RSTRIDE + c4 * 8;
        *(uint2*)(smem + SM_AHI + off) = make_uint2(h0, h1);
        *(uint2*)(smem + SM_ALO + off) = make_uint2(l0, l1);
    }
    // ---- fill B (128x128 bf16 copy), 2048 uint4 per plane / 256 thr ----
    #pragma unroll
    for (int it = 0; it < 8; ++it) {
        int idx = it * 256 + tid;
        int row = idx >> 4, c8 = idx & 15;
        uint32_t off = row * RSTRIDE + c8 * 16;
        size_t s = (size_t)row * EMBED + c8 * 8;
        *(uint4*)(smem + SM_BHI + off) = *(const uint4*)(Bh + s);
        *(uint4*)(smem + SM_BLO + off) = *(const uint4*)(Bl + s);
    }
    __syncthreads();

    // A x4 fragments (m16k16): lanes 0-7 m0-7 k0 | 8-15 m8-15 k0 | 16-23 m0-7 k8 | 24-31 m8-15 k8
    const int arow = mw * 32 + (lane & 7) + ((lane >> 3) & 1) * 8;
    const uint32_t akb = ((lane >> 4) & 1) * 16;
    uint32_t aHi[2], aLo[2];
    #pragma unroll
    for (int mt = 0; mt < 2; ++mt) {
        uint32_t ro = (arow + mt * 16) * RSTRIDE + akb;
        aHi[mt] = sbase + SM_AHI + ro;
        aLo[mt] = sbase + SM_ALO + ro;
    }
    // B x4 fragments (n16k16): lanes 0-7 n0-7 k0 | 8-15 n0-7 k8 | 16-23 n8-15 k0 | 24-31 n8-15 k8
    const int brow = nw2 * 32 + (lane & 7) + (lane >> 4) * 8;
    const uint32_t bkb = ((lane >> 3) & 1) * 16;
    uint32_t bHi[2], bLo[2];
    #pragma unroll
    for (int q = 0; q < 2; ++q) {
        uint32_t ro = (brow + q * 16) * RSTRIDE + bkb;
        bHi[q] = sbase + SM_BHI + ro;
        bLo[q] = sbase + SM_BLO + ro;
    }

    float acc[2][4][4];
    #pragma unroll
    for (int mt = 0; mt < 2; ++mt)
        #pragma unroll
        for (int nt = 0; nt < 4; ++nt)
            #pragma unroll
            for (int c = 0; c < 4; ++c) acc[mt][nt][c] = 0.f;

    // ---- main loop: 8 k-steps of 16 ----
    #pragma unroll
    for (int kt = 0; kt < 8; ++kt) {
        const uint32_t ko = kt * 32;
        uint32_t ah[2][4], al[2][4], bh[2][4], bl[2][4];
        #pragma unroll
        for (int mt = 0; mt < 2; ++mt) {
            LDM4(ah[mt], aHi[mt] + ko);
            LDM4(al[mt], aLo[mt] + ko);
        }
        #pragma unroll
        for (int q = 0; q < 2; ++q) {
            LDM4(bh[q], bHi[q] + ko);
            LDM4(bl[q], bLo[q] + ko);
        }
        #pragma unroll
        for (int mt = 0; mt < 2; ++mt)
            #pragma unroll
            for (int nt = 0; nt < 4; ++nt) {
                const int q = nt >> 1, r = (nt & 1) * 2;
                MMA_BF16(acc[mt][nt], ah[mt], bh[q][r], bh[q][r + 1]);
                MMA_BF16(acc[mt][nt], ah[mt], bl[q][r], bl[q][r + 1]);
                MMA_BF16(acc[mt][nt], al[mt], bh[q][r], bh[q][r + 1]);
            }
    }

    // ---- epilogue ----
    #pragma unroll
    for (int mt = 0; mt < 2; ++mt)
        #pragma unroll
        for (int nt = 0; nt < 4; ++nt) {
            const float* c = acc[mt][nt];
            const int col = n0 + nw2 * 32 + nt * 8 + (lane & 3) * 2;
            const int r0  = m0 + mw * 32 + mt * 16 + (lane >> 2);
            float2 bv = *(const float2*)(bias + col);
            float2 lo = make_float2(c[0] + bv.x, c[1] + bv.y);
            float2 hi = make_float2(c[2] + bv.x, c[3] + bv.y);
            if (QKV) {
                const int s = col >> 7, hh2 = (col >> 5) & 3, d = col & 31;
                float* p0 = g_qkv + ((size_t)(s * 16 + b * 4 + hh2) * TOK + r0) * HD + d;
                *(float2*)p0 = lo;
                *(float2*)(p0 + 8 * HD) = hi;
            } else {
                float* p0 = outp + (size_t)r0 * EMBED + col;
                *(float2*)p0 = lo;
                *(float2*)(p0 + 8 * EMBED) = hi;
            }
        }
}

// ---------------- kernel 3: neighborhood attention (best measured) -----------
// R4 layout: 8x16 tile, fp32 planar smem (conflict-free), Taylor exp on FMA
// pipe, p[49] fp32. Measured 45.4us.
#define TILE_I 8
#define TILE_J 16
#define HALO_I 14
#define HALO_J 22
#define NPOS   (HALO_I * HALO_J)        // 308 positions
#define NF4    (NPOS * 8)               // 2464 float4 per tensor
#define PLANE  1252                     // floats per plane, ==4 mod 32
#define ATTN_SMEM (8 * PLANE * 4)       // 40064 bytes

__global__ __launch_bounds__(128, 4) void attn_kernel() {
    extern __shared__ float smemf[];

    const int tid = threadIdx.x;
    const int z = blockIdx.z;             // b*4 + h
    const int b = z >> 2, h = z & 3;
    const int j0 = blockIdx.x * TILE_J;
    const int i0 = blockIdx.y * TILE_I;

    const int bh = b * 4 + h;
    const float* qg = g_qkv + (size_t)bh * TOK * HD;          // s=0
    const float* kg = g_qkv + (size_t)(16 + bh) * TOK * HD;   // s=1
    const float* vg = g_qkv + (size_t)(32 + bh) * TOK * HD;   // s=2

    const int li = tid >> 4;     // 0..7
    const int lj = tid & 15;     // 0..15
    const int gi = i0 + li, gj = j0 + lj;

    #pragma unroll 1
    for (int idx = tid; idx < NF4; idx += 128) {
        int pos = idx >> 3, f = idx & 7;
        int r = pos / HALO_J, c = pos - r * HALO_J;
        int ri = i0 - PAD + r, rj = j0 - PAD + c;
        float4 kv = make_float4(0.f, 0.f, 0.f, 0.f);
        if (ri >= 0 && ri < HH && rj >= 0 && rj < WW)
            kv = *(const float4*)(kg + ((size_t)(ri * WW + rj)) * HD + f * 4);
        *(float4*)(smemf + f * PLANE + pos * 4) = kv;
    }

    float4 rq[8];
    {
        const float4* qp = (const float4*)(qg + ((size_t)(gi * WW + gj)) * HD);
        #pragma unroll
        for (int q = 0; q < 8; ++q) {
            float4 v = qp[q];
            rq[q] = make_float4(v.x * SCALE, v.y * SCALE, v.z * SCALE, v.w * SCALE);
        }
    }
    __syncthreads();

    // ---- pass 1: logits -> p[49] = exp(logit) via FMA-pipe polynomial ----
    float p[K2];
    float den = 0.f;
    #pragma unroll
    for (int di = 0; di < KER; ++di) {
        #pragma unroll
        for (int dj = 0; dj < KER; ++dj) {
            const int pos4 = ((li + di) * HALO_J + (lj + dj)) * 4;
            float d0 = 0.f, d1 = 0.f, d2 = 0.f, d3 = 0.f;
            #pragma unroll
            for (int q = 0; q < 8; ++q) {
                float4 kv = *(const float4*)(smemf + q * PLANE + pos4);
                d0 = fmaf(rq[q].x, kv.x, d0);
                d1 = fmaf(rq[q].y, kv.y, d1);
                d2 = fmaf(rq[q].z, kv.z, d2);
                d3 = fmaf(rq[q].w, kv.w, d3);
            }
            const float xv = (d0 + d1) + (d2 + d3);
            float t = fmaf(xv, 1.f / 40320.f, 1.f / 5040.f);
            t = fmaf(t, xv, 1.f / 720.f);
            t = fmaf(t, xv, 1.f / 120.f);
            t = fmaf(t, xv, 1.f / 24.f);
            t = fmaf(t, xv, 1.f / 6.f);
            t = fmaf(t, xv, 0.5f);
            t = fmaf(t, xv, 1.f);
            const float e = fmaf(xv, t, 1.f);
            p[di * KER + dj] = e;
            den += e;
        }
    }
    __syncthreads();

    #pragma unroll 1
    for (int idx = tid; idx < NF4; idx += 128) {
        int pos = idx >> 3, f = idx & 7;
        int r = pos / HALO_J, c = pos - r * HALO_J;
        int ri = i0 - PAD + r, rj = j0 - PAD + c;
        float4 vv = make_float4(0.f, 0.f, 0.f, 0.f);
        if (ri >= 0 && ri < HH && rj >= 0 && rj < WW)
            vv = *(const float4*)(vg + ((size_t)(ri * WW + rj)) * HD + f * 4);
        *(float4*)(smemf + f * PLANE + pos * 4) = vv;
    }
    __syncthreads();

    float4 acc[8];
    #pragma unroll
    for (int q = 0; q < 8; ++q) acc[q] = make_float4(0.f, 0.f, 0.f, 0.f);

    #pragma unroll
    for (int di = 0; di < KER; ++di) {
        #pragma unroll
        for (int dj = 0; dj < KER; ++dj) {
            const int pos4 = ((li + di) * HALO_J + (lj + dj)) * 4;
            const float pw = p[di * KER + dj];
            #pragma unroll
            for (int q = 0; q < 8; ++q) {
                float4 vv = *(const float4*)(smemf + q * PLANE + pos4);
                acc[q].x = fmaf(pw, vv.x, acc[q].x);
                acc[q].y = fmaf(pw, vv.y, acc[q].y);
                acc[q].z = fmaf(pw, vv.z, acc[q].z);
                acc[q].w = fmaf(pw, vv.w, acc[q].w);
            }
        }
    }

    const float inv = 1.f / den;
    float* op = g_attn + ((size_t)(b * TOK + gi * WW + gj)) * EMBED + h * HD;
    #pragma unroll
    for (int q = 0; q < 8; ++q) {
        float4 r = make_float4(acc[q].x * inv, acc[q].y * inv,
                               acc[q].z * inv, acc[q].w * inv);
        *(float4*)(op + q * 4) = r;
    }
}

// ---------------- launch -----------------------------------------------------
extern "C" void kernel_launch(void* const* d_in, const int* in_sizes, int n_in,
                              void* d_out, int out_size) {
    const float* x     = (const float*)d_in[0];
    const float* ctx   = (const float*)d_in[1];
    const float* Wqkv  = (const float*)d_in[2];
    const float* bqkv  = (const float*)d_in[3];
    const float* A     = (const float*)d_in[4];
    const float* Blora = (const float*)d_in[5];
    const float* Vlora = (const float*)d_in[6];
    const float* g1w   = (const float*)d_in[7];
    const float* g1b   = (const float*)d_in[8];
    const float* g2w   = (const float*)d_in[9];
    const float* g2b   = (const float*)d_in[10];
    const float* Wproj = (const float*)d_in[11];
    const float* bproj = (const float*)d_in[12];
    float* out = (float*)d_out;

    cudaFuncSetAttribute(attn_kernel,
                         cudaFuncAttributeMaxDynamicSharedMemorySize, ATTN_SMEM);
    cudaFuncSetAttribute(gemm_mma<true>,
                         cudaFuncAttributeMaxDynamicSharedMemorySize, GEMM_SMEM);
    cudaFuncSetAttribute(gemm_mma<false>,
                         cudaFuncAttributeMaxDynamicSharedMemorySize, GEMM_SMEM);

    prep_kernel<<<1, 128>>>(ctx, Blora, g1w, g1b, g2w, g2b);
    weff_kernel<<<208, 256>>>(Wqkv, A, Vlora, Wproj);
    // qkv: M=4096 (64 tiles of 64) x N=384 (3 tiles of 128) per batch
    gemm_mma<true><<<dim3(64, 3, 4), 256, GEMM_SMEM>>>(x, bqkv, nullptr);
    attn_kernel<<<dim3(WW / TILE_J, HH / TILE_I, NB * NH), 128, ATTN_SMEM>>>();
    // proj: M=16384 (256 tiles of 64) x N=128 (1 tile)
    gemm_mma<false><<<dim3(256, 1, 1), 256, GEMM_SMEM>>>(g_attn, bproj, out);
}